// round 12
// baseline (speedup 1.0000x reference)
#include <cuda_runtime.h>
#include <math.h>

#define NN 100000
#define NE 1600000
#define ET (NE + NN)        // edges incl. self loops
#define HD 64
#define NC 16
#define NBLK ((NN + 255) / 256)   // 391

// ---------------- scratch (device globals; no allocation allowed) ----------
__device__ __align__(16) int   g_srcs[ET];       // CSR: src per edge, grouped by dst
__device__ int   g_rowstart[NN + 1];
__device__ int   g_deg[NN];                      // zero at load; re-zeroed by scan1
__device__ int   g_cursor[NN];
__device__ int   g_bsums[512];
__device__ __align__(16) float g_h[NN * HD];     // transformed features (fp32)
__device__ __align__(16) float g_x1[NN * HD];    // layer-1 output (after elu)
__device__ __align__(16) float g_x2[NN * HD];    // fallback layer-2 output
__device__ float g_as[NN];
__device__ float g_ad[NN];

__device__ __forceinline__ int clampN(int v) {
    return (v < 0) ? 0 : (v >= NN ? NN - 1 : v);
}

// ---------------- CSR build ------------------------------------------------
__global__ void k_hist(const int* __restrict__ adj) {
    int i = blockIdx.x * blockDim.x + threadIdx.x;
    int stride = gridDim.x * blockDim.x;
    for (int e = i; e < NE; e += stride)
        atomicAdd(&g_deg[clampN(adj[NE + e])], 1);
}

__global__ void k_scan1() {
    __shared__ int sh[256];
    int t = threadIdx.x;
    int idx = blockIdx.x * 256 + t;
    int v = 0;
    if (idx < NN) {
        v = g_deg[idx] + 1;      // +1: self loop
        g_deg[idx] = 0;          // reset for next graph replay
    }
    int x = v;
    sh[t] = x;
    __syncthreads();
    #pragma unroll
    for (int off = 1; off < 256; off <<= 1) {
        int y = (t >= off) ? sh[t - off] : 0;
        __syncthreads();
        x += y;
        sh[t] = x;
        __syncthreads();
    }
    if (idx < NN) g_rowstart[idx] = x - v;   // exclusive, partial
    if (t == 255) g_bsums[blockIdx.x] = x;   // block total
}

__global__ void k_scan2() {
    __shared__ int sh[512];
    int t = threadIdx.x;
    int v = (t < NBLK) ? g_bsums[t] : 0;
    int x = v;
    sh[t] = x;
    __syncthreads();
    #pragma unroll
    for (int off = 1; off < 512; off <<= 1) {
        int y = (t >= off) ? sh[t - off] : 0;
        __syncthreads();
        x += y;
        sh[t] = x;
        __syncthreads();
    }
    if (t < NBLK) g_bsums[t] = x - v;        // exclusive
    if (t == 511) g_rowstart[NN] = x;        // total == ET
}

__global__ void k_scan3() {
    int idx = blockIdx.x * 256 + threadIdx.x;
    if (idx < NN) {
        int r = g_rowstart[idx] + g_bsums[idx >> 8];
        g_rowstart[idx] = r;
        g_cursor[idx] = r;
    }
}

__global__ void k_scatter(const int* __restrict__ adj) {
    int i = blockIdx.x * blockDim.x + threadIdx.x;
    int stride = gridDim.x * blockDim.x;
    for (int e = i; e < ET; e += stride) {
        int s, d;
        if (e < NE) { s = clampN(adj[e]); d = clampN(adj[NE + e]); }
        else        { s = d = e - NE; }
        int pos = atomicAdd(&g_cursor[d], 1);
        g_srcs[pos] = s;
    }
}

// ---------------- fused GEMM (h = X@W) + alpha dots ------------------------
template <int K, bool FROM_G>
__global__ void __launch_bounds__(256) k_gemm(
    const float* __restrict__ Xext, const float* __restrict__ W,
    const float* __restrict__ asrc, const float* __restrict__ adst)
{
    __shared__ float Xs[64 * 68];
    __shared__ float Ws[64 * 66];

    const float* X = FROM_G ? g_x1 : Xext;

    int tid = threadIdx.x;
    int ty = tid >> 4;
    int tx = tid & 15;
    int nbase = blockIdx.x * 64;

    float acc[4][4];
    #pragma unroll
    for (int i = 0; i < 4; i++)
        #pragma unroll
        for (int j = 0; j < 4; j++) acc[i][j] = 0.f;

    for (int kt = 0; kt < K; kt += 64) {
        #pragma unroll
        for (int i = 0; i < 4; i++) {
            int idx = tid + i * 256;
            int r = idx >> 4;
            int c4 = idx & 15;
            int rg = nbase + r;
            if (rg >= NN) rg = NN - 1;
            float4 v = *(const float4*)(X + (size_t)rg * K + kt + c4 * 4);
            *(float4*)(Xs + r * 68 + c4 * 4) = v;
        }
        #pragma unroll
        for (int i = 0; i < 16; i++) {
            int idx = tid + i * 256;
            int kk = idx >> 6;
            int c  = idx & 63;
            Ws[c * 66 + kk] = W[(kt + kk) * 64 + c];
        }
        __syncthreads();

        #pragma unroll
        for (int kk = 0; kk < 64; kk += 4) {
            float4 xv[4];
            #pragma unroll
            for (int i = 0; i < 4; i++)
                xv[i] = *(const float4*)(Xs + (i * 16 + ty) * 68 + kk);
            float4 wv[4];
            #pragma unroll
            for (int j = 0; j < 4; j++) {
                float2 a = *(const float2*)(Ws + (j * 16 + tx) * 66 + kk);
                float2 b = *(const float2*)(Ws + (j * 16 + tx) * 66 + kk + 2);
                wv[j] = make_float4(a.x, a.y, b.x, b.y);
            }
            #pragma unroll
            for (int i = 0; i < 4; i++)
                #pragma unroll
                for (int j = 0; j < 4; j++) {
                    acc[i][j] += xv[i].x * wv[j].x;
                    acc[i][j] += xv[i].y * wv[j].y;
                    acc[i][j] += xv[i].z * wv[j].z;
                    acc[i][j] += xv[i].w * wv[j].w;
                }
        }
        __syncthreads();
    }

    float asc[4], adc[4];
    #pragma unroll
    for (int j = 0; j < 4; j++) {
        int col = j * 16 + tx;
        asc[j] = asrc[col];
        adc[j] = adst[col];
    }
    #pragma unroll
    for (int i = 0; i < 4; i++) {
        int node = nbase + i * 16 + ty;
        float ps = 0.f, pd = 0.f;
        #pragma unroll
        for (int j = 0; j < 4; j++) {
            ps += acc[i][j] * asc[j];
            pd += acc[i][j] * adc[j];
        }
        #pragma unroll
        for (int off = 8; off; off >>= 1) {
            ps += __shfl_xor_sync(0xffffffffu, ps, off);
            pd += __shfl_xor_sync(0xffffffffu, pd, off);
        }
        if (node < NN) {
            #pragma unroll
            for (int j = 0; j < 4; j++)
                g_h[(size_t)node * 64 + j * 16 + tx] = acc[i][j];
            if (tx == 0) { g_as[node] = ps; g_ad[node] = pd; }
        }
    }
}

// ---------------- GAT aggregation: one warp per destination node -----------
// Unshifted softmax (ratio identical to max-shifted; logits Xavier-scaled,
// |e| << 88 so no overflow). Lane covers dims {2*lane, 2*lane+1} via LDG.64.
// int4 srcs loads + 8-edge unroll: 8 independent gather chains per iteration.
// MODE 0: write external out (no elu); MODE 1: g_x1 (elu); MODE 2: g_x2.
template <int MODE>
__global__ void __launch_bounds__(256) k_agg(
    const float* __restrict__ bias, float* __restrict__ outext)
{
    int warp = (blockIdx.x * blockDim.x + threadIdx.x) >> 5;
    int lane = threadIdx.x & 31;
    if (warp >= NN) return;

    float* out = (MODE == 1) ? g_x1 : (MODE == 2 ? g_x2 : outext);

    int beg = g_rowstart[warp];
    int end = g_rowstart[warp + 1];
    float adr = g_ad[warp];

    float ssum = 0.f, a0 = 0.f, a1 = 0.f;
    int e = beg;
    // peel to 16B alignment for int4 loads
    for (; e < end && (e & 3); e++) {
        int s = g_srcs[e];
        float v = g_as[s] + adr;
        v = (v > 0.f) ? v : 0.2f * v;
        float p = __expf(v);
        float2 h = ((const float2*)(g_h + (size_t)s * 64))[lane];
        ssum += p;
        a0 += p * h.x;
        a1 += p * h.y;
    }
    // 8-edge unroll: 2 int4 src loads, 8 parallel alpha + feature gathers
    for (; e + 8 <= end; e += 8) {
        int4 sa = *(const int4*)(g_srcs + e);
        int4 sb = *(const int4*)(g_srcs + e + 4);
        float va0 = g_as[sa.x], va1 = g_as[sa.y], va2 = g_as[sa.z], va3 = g_as[sa.w];
        float vb0 = g_as[sb.x], vb1 = g_as[sb.y], vb2 = g_as[sb.z], vb3 = g_as[sb.w];
        float2 ha0 = ((const float2*)(g_h + (size_t)sa.x * 64))[lane];
        float2 ha1 = ((const float2*)(g_h + (size_t)sa.y * 64))[lane];
        float2 ha2 = ((const float2*)(g_h + (size_t)sa.z * 64))[lane];
        float2 ha3 = ((const float2*)(g_h + (size_t)sa.w * 64))[lane];
        float2 hb0 = ((const float2*)(g_h + (size_t)sb.x * 64))[lane];
        float2 hb1 = ((const float2*)(g_h + (size_t)sb.y * 64))[lane];
        float2 hb2 = ((const float2*)(g_h + (size_t)sb.z * 64))[lane];
        float2 hb3 = ((const float2*)(g_h + (size_t)sb.w * 64))[lane];
        va0 += adr; va1 += adr; va2 += adr; va3 += adr;
        vb0 += adr; vb1 += adr; vb2 += adr; vb3 += adr;
        va0 = (va0 > 0.f) ? va0 : 0.2f * va0;
        va1 = (va1 > 0.f) ? va1 : 0.2f * va1;
        va2 = (va2 > 0.f) ? va2 : 0.2f * va2;
        va3 = (va3 > 0.f) ? va3 : 0.2f * va3;
        vb0 = (vb0 > 0.f) ? vb0 : 0.2f * vb0;
        vb1 = (vb1 > 0.f) ? vb1 : 0.2f * vb1;
        vb2 = (vb2 > 0.f) ? vb2 : 0.2f * vb2;
        vb3 = (vb3 > 0.f) ? vb3 : 0.2f * vb3;
        float pa0 = __expf(va0), pa1 = __expf(va1);
        float pa2 = __expf(va2), pa3 = __expf(va3);
        float pb0 = __expf(vb0), pb1 = __expf(vb1);
        float pb2 = __expf(vb2), pb3 = __expf(vb3);
        ssum += ((pa0 + pa1) + (pa2 + pa3)) + ((pb0 + pb1) + (pb2 + pb3));
        a0 += pa0 * ha0.x + pa1 * ha1.x + pa2 * ha2.x + pa3 * ha3.x
            + pb0 * hb0.x + pb1 * hb1.x + pb2 * hb2.x + pb3 * hb3.x;
        a1 += pa0 * ha0.y + pa1 * ha1.y + pa2 * ha2.y + pa3 * ha3.y
            + pb0 * hb0.y + pb1 * hb1.y + pb2 * hb2.y + pb3 * hb3.y;
    }
    // 4-edge tail
    for (; e + 4 <= end; e += 4) {
        int4 s4 = *(const int4*)(g_srcs + e);
        float v0 = g_as[s4.x], v1 = g_as[s4.y], v2 = g_as[s4.z], v3 = g_as[s4.w];
        float2 h0 = ((const float2*)(g_h + (size_t)s4.x * 64))[lane];
        float2 h1 = ((const float2*)(g_h + (size_t)s4.y * 64))[lane];
        float2 h2 = ((const float2*)(g_h + (size_t)s4.z * 64))[lane];
        float2 h3 = ((const float2*)(g_h + (size_t)s4.w * 64))[lane];
        v0 += adr; v1 += adr; v2 += adr; v3 += adr;
        v0 = (v0 > 0.f) ? v0 : 0.2f * v0;
        v1 = (v1 > 0.f) ? v1 : 0.2f * v1;
        v2 = (v2 > 0.f) ? v2 : 0.2f * v2;
        v3 = (v3 > 0.f) ? v3 : 0.2f * v3;
        float p0 = __expf(v0), p1 = __expf(v1);
        float p2 = __expf(v2), p3 = __expf(v3);
        ssum += (p0 + p1) + (p2 + p3);
        a0 += p0 * h0.x + p1 * h1.x + p2 * h2.x + p3 * h3.x;
        a1 += p0 * h0.y + p1 * h1.y + p2 * h2.y + p3 * h3.y;
    }
    // scalar tail
    for (; e < end; e++) {
        int s = g_srcs[e];
        float v = g_as[s] + adr;
        v = (v > 0.f) ? v : 0.2f * v;
        float p = __expf(v);
        float2 h = ((const float2*)(g_h + (size_t)s * 64))[lane];
        ssum += p;
        a0 += p * h.x;
        a1 += p * h.y;
    }

    float2 bv = ((const float2*)bias)[lane];
    float inv = 1.0f / ssum;
    float o0 = a0 * inv + bv.x;
    float o1 = a1 * inv + bv.y;
    if (MODE == 1) {
        o0 = (o0 > 0.f) ? o0 : expm1f(o0);
        o1 = (o1 > 0.f) ? o1 : expm1f(o1);
    }
    ((float2*)(out + (size_t)warp * 64))[lane] = make_float2(o0, o1);
}

// ---------------- classifier ------------------------------------------------
template <bool FROM_G>
__global__ void __launch_bounds__(256) k_clf(
    const float* __restrict__ xext, const float* __restrict__ Wc,
    const float* __restrict__ bc, float* __restrict__ out)
{
    __shared__ float Ws[64 * 16];
    int tid = threadIdx.x;
    for (int i = tid; i < 64 * 16; i += 256) Ws[i] = Wc[i];
    __syncthreads();

    const float* x = FROM_G ? g_x2 : xext;

    int node = blockIdx.x * 16 + (tid >> 4);
    int col = tid & 15;
    if (node >= NN) return;
    float acc = bc[col];
    const float* xr = x + (size_t)node * 64;
    #pragma unroll
    for (int k = 0; k < 64; k += 4) {
        float4 xv = *(const float4*)(xr + k);
        acc += xv.x * Ws[(k + 0) * 16 + col];
        acc += xv.y * Ws[(k + 1) * 16 + col];
        acc += xv.z * Ws[(k + 2) * 16 + col];
        acc += xv.w * Ws[(k + 3) * 16 + col];
    }
    out[(size_t)node * 16 + col] = acc;
}

// ---------------- launch -----------------------------------------------------
extern "C" void kernel_launch(void* const* d_in, const int* in_sizes, int n_in,
                              void* d_out, int out_size) {
    const float* ft  = (const float*)d_in[0];
    const int*   adj = (const int*)d_in[1];     // int32 (JAX x64 disabled)
    const float* W1  = (const float*)d_in[2];
    const float* as1 = (const float*)d_in[3];
    const float* ad1 = (const float*)d_in[4];
    const float* b1  = (const float*)d_in[5];
    const float* W2  = (const float*)d_in[6];
    const float* as2 = (const float*)d_in[7];
    const float* ad2 = (const float*)d_in[8];
    const float* b2  = (const float*)d_in[9];
    const float* Wc  = (const float*)d_in[10];
    const float* bc  = (const float*)d_in[11];
    float* out = (float*)d_out;

    bool big_out = (out_size >= NN * (NC + HD));
    float* xout = out + (size_t)NN * NC;   // only used when big_out

    static cudaStream_t s_side = nullptr;
    static cudaEvent_t  ev_fork = nullptr, ev_join = nullptr;
    if (s_side == nullptr) {
        cudaStreamCreateWithFlags(&s_side, cudaStreamNonBlocking);
        cudaEventCreateWithFlags(&ev_fork, cudaEventDisableTiming);
        cudaEventCreateWithFlags(&ev_join, cudaEventDisableTiming);
    }

    int gemm_blocks = (NN + 63) / 64;        // 1563
    int agg_blocks  = (NN * 32 + 255) / 256; // 12500
    int hist_blocks = (NE + 255) / 256;      // 6250
    int scat_blocks = (ET + 255) / 256;      // 6641

    // fork: CSR build on side stream, concurrent with layer-1 GEMM
    cudaEventRecord(ev_fork, 0);
    cudaStreamWaitEvent(s_side, ev_fork, 0);

    k_hist<<<hist_blocks, 256, 0, s_side>>>(adj);
    k_scan1<<<NBLK, 256, 0, s_side>>>();
    k_scan2<<<1, 512, 0, s_side>>>();
    k_scan3<<<NBLK, 256, 0, s_side>>>();
    k_scatter<<<scat_blocks, 256, 0, s_side>>>(adj);
    cudaEventRecord(ev_join, s_side);

    // main stream: layer-1 GEMM overlaps CSR build
    k_gemm<128, false><<<gemm_blocks, 256>>>(ft, W1, as1, ad1);

    cudaStreamWaitEvent(0, ev_join, 0);
    k_agg<1><<<agg_blocks, 256>>>(b1, nullptr);

    // layer 2
    k_gemm<64, true><<<gemm_blocks, 256>>>(nullptr, W2, as2, ad2);
    if (big_out) {
        k_agg<0><<<agg_blocks, 256>>>(b2, xout);
        k_clf<false><<<(NN + 15) / 16, 256>>>(xout, Wc, bc, out);
    } else {
        k_agg<2><<<agg_blocks, 256>>>(b2, nullptr);
        k_clf<true><<<(NN + 15) / 16, 256>>>(nullptr, Wc, bc, out);
    }
}

// round 13
// speedup vs baseline: 1.0177x; 1.0177x over previous
#include <cuda_runtime.h>
#include <math.h>

#define NN 100000
#define NE 1600000
#define ET (NE + NN)        // edges incl. self loops
#define HD 64
#define NC 16
#define NBLK ((NN + 255) / 256)   // 391

// ---------------- scratch (device globals; no allocation allowed) ----------
__device__ __align__(16) int   g_srcs[ET];       // CSR: src per edge, grouped by dst
__device__ int   g_rowstart[NN + 1];
__device__ int   g_deg[NN];                      // zero at load; re-zeroed by scan1
__device__ int   g_cursor[NN];
__device__ int   g_bsums[512];
__device__ __align__(16) float g_h[NN * HD];     // transformed features (fp32)
__device__ __align__(16) float g_x1[NN * HD];    // layer-1 output (after elu)
__device__ __align__(16) float g_x2[NN * HD];    // fallback layer-2 output
__device__ float g_as[NN];
__device__ float g_ad[NN];

__device__ __forceinline__ int clampN(int v) {
    return (v < 0) ? 0 : (v >= NN ? NN - 1 : v);
}

// ---------------- CSR build ------------------------------------------------
__global__ void k_hist(const int* __restrict__ adj) {
    int i = blockIdx.x * blockDim.x + threadIdx.x;
    int stride = gridDim.x * blockDim.x;
    for (int e = i; e < NE; e += stride)
        atomicAdd(&g_deg[clampN(adj[NE + e])], 1);
}

__global__ void k_scan1() {
    __shared__ int sh[256];
    int t = threadIdx.x;
    int idx = blockIdx.x * 256 + t;
    int v = 0;
    if (idx < NN) {
        v = g_deg[idx] + 1;      // +1: self loop
        g_deg[idx] = 0;          // reset for next graph replay
    }
    int x = v;
    sh[t] = x;
    __syncthreads();
    #pragma unroll
    for (int off = 1; off < 256; off <<= 1) {
        int y = (t >= off) ? sh[t - off] : 0;
        __syncthreads();
        x += y;
        sh[t] = x;
        __syncthreads();
    }
    if (idx < NN) g_rowstart[idx] = x - v;   // exclusive, partial
    if (t == 255) g_bsums[blockIdx.x] = x;   // block total
}

// scan2+scan3 merged: each block redundantly computes the prefix of the
// <=391 block sums it needs (trivial work), then finalizes rowstart/cursor.
__global__ void k_scan23() {
    __shared__ int sh[256];
    int b = blockIdx.x, t = threadIdx.x;

    // sum of g_bsums[j] for j < b  (each thread covers j = t and t+256)
    int s = 0;
    if (t < b) s += g_bsums[t];
    int t2 = t + 256;
    if (t2 < b) s += g_bsums[t2];
    sh[t] = s;
    __syncthreads();
    #pragma unroll
    for (int off = 128; off; off >>= 1) {
        if (t < off) sh[t] += sh[t + off];
        __syncthreads();
    }
    int base = sh[0];

    int idx = b * 256 + t;
    if (idx < NN) {
        int r = g_rowstart[idx] + base;
        g_rowstart[idx] = r;
        g_cursor[idx] = r;
    }
    if (b == NBLK - 1 && t == 0)
        g_rowstart[NN] = base + g_bsums[NBLK - 1];   // total == ET
}

__global__ void k_scatter(const int* __restrict__ adj) {
    int i = blockIdx.x * blockDim.x + threadIdx.x;
    int stride = gridDim.x * blockDim.x;
    for (int e = i; e < ET; e += stride) {
        int s, d;
        if (e < NE) { s = clampN(adj[e]); d = clampN(adj[NE + e]); }
        else        { s = d = e - NE; }
        int pos = atomicAdd(&g_cursor[d], 1);
        g_srcs[pos] = s;
    }
}

// ---------------- fused GEMM (h = X@W) + alpha dots ------------------------
template <int K, bool FROM_G>
__global__ void __launch_bounds__(256) k_gemm(
    const float* __restrict__ Xext, const float* __restrict__ W,
    const float* __restrict__ asrc, const float* __restrict__ adst)
{
    __shared__ float Xs[64 * 68];
    __shared__ float Ws[64 * 66];

    const float* X = FROM_G ? g_x1 : Xext;

    int tid = threadIdx.x;
    int ty = tid >> 4;
    int tx = tid & 15;
    int nbase = blockIdx.x * 64;

    float acc[4][4];
    #pragma unroll
    for (int i = 0; i < 4; i++)
        #pragma unroll
        for (int j = 0; j < 4; j++) acc[i][j] = 0.f;

    for (int kt = 0; kt < K; kt += 64) {
        #pragma unroll
        for (int i = 0; i < 4; i++) {
            int idx = tid + i * 256;
            int r = idx >> 4;
            int c4 = idx & 15;
            int rg = nbase + r;
            if (rg >= NN) rg = NN - 1;
            float4 v = *(const float4*)(X + (size_t)rg * K + kt + c4 * 4);
            *(float4*)(Xs + r * 68 + c4 * 4) = v;
        }
        #pragma unroll
        for (int i = 0; i < 16; i++) {
            int idx = tid + i * 256;
            int kk = idx >> 6;
            int c  = idx & 63;
            Ws[c * 66 + kk] = W[(kt + kk) * 64 + c];
        }
        __syncthreads();

        #pragma unroll
        for (int kk = 0; kk < 64; kk += 4) {
            float4 xv[4];
            #pragma unroll
            for (int i = 0; i < 4; i++)
                xv[i] = *(const float4*)(Xs + (i * 16 + ty) * 68 + kk);
            float4 wv[4];
            #pragma unroll
            for (int j = 0; j < 4; j++) {
                float2 a = *(const float2*)(Ws + (j * 16 + tx) * 66 + kk);
                float2 b = *(const float2*)(Ws + (j * 16 + tx) * 66 + kk + 2);
                wv[j] = make_float4(a.x, a.y, b.x, b.y);
            }
            #pragma unroll
            for (int i = 0; i < 4; i++)
                #pragma unroll
                for (int j = 0; j < 4; j++) {
                    acc[i][j] += xv[i].x * wv[j].x;
                    acc[i][j] += xv[i].y * wv[j].y;
                    acc[i][j] += xv[i].z * wv[j].z;
                    acc[i][j] += xv[i].w * wv[j].w;
                }
        }
        __syncthreads();
    }

    float asc[4], adc[4];
    #pragma unroll
    for (int j = 0; j < 4; j++) {
        int col = j * 16 + tx;
        asc[j] = asrc[col];
        adc[j] = adst[col];
    }
    #pragma unroll
    for (int i = 0; i < 4; i++) {
        int node = nbase + i * 16 + ty;
        float ps = 0.f, pd = 0.f;
        #pragma unroll
        for (int j = 0; j < 4; j++) {
            ps += acc[i][j] * asc[j];
            pd += acc[i][j] * adc[j];
        }
        #pragma unroll
        for (int off = 8; off; off >>= 1) {
            ps += __shfl_xor_sync(0xffffffffu, ps, off);
            pd += __shfl_xor_sync(0xffffffffu, pd, off);
        }
        if (node < NN) {
            #pragma unroll
            for (int j = 0; j < 4; j++)
                g_h[(size_t)node * 64 + j * 16 + tx] = acc[i][j];
            if (tx == 0) { g_as[node] = ps; g_ad[node] = pd; }
        }
    }
}

// ---------------- GAT aggregation: one warp per destination node -----------
// Unshifted softmax (ratio identical to max-shifted; logits Xavier-scaled,
// |e| << 88 so no overflow). Lane covers dims {2*lane, 2*lane+1} via LDG.64.
// 4-edge unroll: batch index loads -> alpha gathers -> feature gathers.
// MODE 0: write external out (no elu); MODE 1: g_x1 (elu); MODE 2: g_x2.
template <int MODE>
__global__ void __launch_bounds__(256) k_agg(
    const float* __restrict__ bias, float* __restrict__ outext)
{
    int warp = (blockIdx.x * blockDim.x + threadIdx.x) >> 5;
    int lane = threadIdx.x & 31;
    if (warp >= NN) return;

    float* out = (MODE == 1) ? g_x1 : (MODE == 2 ? g_x2 : outext);

    int beg = g_rowstart[warp];
    int end = g_rowstart[warp + 1];
    float adr = g_ad[warp];

    float ssum = 0.f, a0 = 0.f, a1 = 0.f;
    int e = beg;
    for (; e + 4 <= end; e += 4) {
        int s0 = g_srcs[e];
        int s1 = g_srcs[e + 1];
        int s2 = g_srcs[e + 2];
        int s3 = g_srcs[e + 3];
        float v0 = g_as[s0];
        float v1 = g_as[s1];
        float v2 = g_as[s2];
        float v3 = g_as[s3];
        float2 h0 = ((const float2*)(g_h + (size_t)s0 * 64))[lane];
        float2 h1 = ((const float2*)(g_h + (size_t)s1 * 64))[lane];
        float2 h2 = ((const float2*)(g_h + (size_t)s2 * 64))[lane];
        float2 h3 = ((const float2*)(g_h + (size_t)s3 * 64))[lane];
        v0 += adr; v1 += adr; v2 += adr; v3 += adr;
        v0 = (v0 > 0.f) ? v0 : 0.2f * v0;
        v1 = (v1 > 0.f) ? v1 : 0.2f * v1;
        v2 = (v2 > 0.f) ? v2 : 0.2f * v2;
        v3 = (v3 > 0.f) ? v3 : 0.2f * v3;
        float p0 = __expf(v0);
        float p1 = __expf(v1);
        float p2 = __expf(v2);
        float p3 = __expf(v3);
        ssum += (p0 + p1) + (p2 + p3);
        a0 += p0 * h0.x + p1 * h1.x + p2 * h2.x + p3 * h3.x;
        a1 += p0 * h0.y + p1 * h1.y + p2 * h2.y + p3 * h3.y;
    }
    for (; e < end; e++) {
        int s = g_srcs[e];
        float v = g_as[s] + adr;
        v = (v > 0.f) ? v : 0.2f * v;
        float p = __expf(v);
        float2 h = ((const float2*)(g_h + (size_t)s * 64))[lane];
        ssum += p;
        a0 += p * h.x;
        a1 += p * h.y;
    }

    float2 bv = ((const float2*)bias)[lane];
    float inv = 1.0f / ssum;
    float o0 = a0 * inv + bv.x;
    float o1 = a1 * inv + bv.y;
    if (MODE == 1) {
        o0 = (o0 > 0.f) ? o0 : expm1f(o0);
        o1 = (o1 > 0.f) ? o1 : expm1f(o1);
    }
    ((float2*)(out + (size_t)warp * 64))[lane] = make_float2(o0, o1);
}

// ---------------- classifier ------------------------------------------------
template <bool FROM_G>
__global__ void __launch_bounds__(256) k_clf(
    const float* __restrict__ xext, const float* __restrict__ Wc,
    const float* __restrict__ bc, float* __restrict__ out)
{
    __shared__ float Ws[64 * 16];
    int tid = threadIdx.x;
    for (int i = tid; i < 64 * 16; i += 256) Ws[i] = Wc[i];
    __syncthreads();

    const float* x = FROM_G ? g_x2 : xext;

    int node = blockIdx.x * 16 + (tid >> 4);
    int col = tid & 15;
    if (node >= NN) return;
    float acc = bc[col];
    const float* xr = x + (size_t)node * 64;
    #pragma unroll
    for (int k = 0; k < 64; k += 4) {
        float4 xv = *(const float4*)(xr + k);
        acc += xv.x * Ws[(k + 0) * 16 + col];
        acc += xv.y * Ws[(k + 1) * 16 + col];
        acc += xv.z * Ws[(k + 2) * 16 + col];
        acc += xv.w * Ws[(k + 3) * 16 + col];
    }
    out[(size_t)node * 16 + col] = acc;
}

// ---------------- launch -----------------------------------------------------
extern "C" void kernel_launch(void* const* d_in, const int* in_sizes, int n_in,
                              void* d_out, int out_size) {
    const float* ft  = (const float*)d_in[0];
    const int*   adj = (const int*)d_in[1];     // int32 (JAX x64 disabled)
    const float* W1  = (const float*)d_in[2];
    const float* as1 = (const float*)d_in[3];
    const float* ad1 = (const float*)d_in[4];
    const float* b1  = (const float*)d_in[5];
    const float* W2  = (const float*)d_in[6];
    const float* as2 = (const float*)d_in[7];
    const float* ad2 = (const float*)d_in[8];
    const float* b2  = (const float*)d_in[9];
    const float* Wc  = (const float*)d_in[10];
    const float* bc  = (const float*)d_in[11];
    float* out = (float*)d_out;

    bool big_out = (out_size >= NN * (NC + HD));
    float* xout = out + (size_t)NN * NC;   // only used when big_out

    static cudaStream_t s_side = nullptr;
    static cudaEvent_t  ev_fork = nullptr, ev_join = nullptr;
    if (s_side == nullptr) {
        cudaStreamCreateWithFlags(&s_side, cudaStreamNonBlocking);
        cudaEventCreateWithFlags(&ev_fork, cudaEventDisableTiming);
        cudaEventCreateWithFlags(&ev_join, cudaEventDisableTiming);
    }

    int gemm_blocks = (NN + 63) / 64;        // 1563
    int agg_blocks  = (NN * 32 + 255) / 256; // 12500
    int hist_blocks = (NE + 255) / 256;      // 6250
    int scat_blocks = (ET + 255) / 256;      // 6641

    // fork: CSR build on side stream, concurrent with layer-1 GEMM.
    // 5 kernels precede agg1 -> ncu (-s 5 -c 1) lands on k_agg<1>.
    cudaEventRecord(ev_fork, 0);
    cudaStreamWaitEvent(s_side, ev_fork, 0);

    k_hist<<<hist_blocks, 256, 0, s_side>>>(adj);
    k_scan1<<<NBLK, 256, 0, s_side>>>();
    k_scan23<<<NBLK, 256, 0, s_side>>>();
    k_scatter<<<scat_blocks, 256, 0, s_side>>>(adj);
    cudaEventRecord(ev_join, s_side);

    // main stream: layer-1 GEMM overlaps CSR build
    k_gemm<128, false><<<gemm_blocks, 256>>>(ft, W1, as1, ad1);

    cudaStreamWaitEvent(0, ev_join, 0);
    k_agg<1><<<agg_blocks, 256>>>(b1, nullptr);

    // layer 2
    k_gemm<64, true><<<gemm_blocks, 256>>>(nullptr, W2, as2, ad2);
    if (big_out) {
        k_agg<0><<<agg_blocks, 256>>>(b2, xout);
        k_clf<false><<<(NN + 15) / 16, 256>>>(xout, Wc, bc, out);
    } else {
        k_agg<2><<<agg_blocks, 256>>>(b2, nullptr);
        k_clf<true><<<(NN + 15) / 16, 256>>>(nullptr, Wc, bc, out);
    }
}